// round 7
// baseline (speedup 1.0000x reference)
#include <cuda_runtime.h>
#include <cuda_fp16.h>
#include <mma.h>
#include <cstdint>

using namespace nvcuda;

#define NNODES 50000
#define NEDGES 600000
#define NREL   8
#define NBASIS 32
#define RN     (NREL * NNODES)
#define SCAN_B 1024
#define NSCAN  ((RN + SCAN_B - 1) / SCAN_B)
#define NK     1152
#define MT256  ((NNODES + 255) / 256)    // 196
#define MPAD   (MT256 * 256)             // 50176
#define KZ     3
#define KCH    12                         // chunks of 32 per kz (3*12*32 = 1152)

// ---------------- static device scratch ----------------
static __device__ __align__(16) __half d_Ahi[(size_t)NNODES * NK];
static __device__ __align__(16) __half d_Alo[(size_t)NNODES * NK];
static __device__ __align__(16) __half d_Bh[128 * NK];           // [n][k]
static __device__ __align__(16) __half d_Ch[512 * 128];          // [n][k]
static __device__ __align__(16) float d_bcat[512];
static __device__ __align__(16) __half d_hhi[(size_t)NNODES * 128];
static __device__ __align__(16) __half d_hlo[(size_t)NNODES * 128];
static __device__ __align__(16) float d_P[KZ * (size_t)MPAD * 128];
static __device__ __align__(16) float d_kskip[(size_t)NNODES * 256];
static __device__ __align__(16) float d_qv[(size_t)NNODES * 256];
static __device__ int d_cnt[RN];
static __device__ int d_off[RN + 1];
static __device__ int d_cur[RN];
static __device__ int d_ssrc[NEDGES];
static __device__ int d_part[SCAN_B];
static __device__ int d_ppre[SCAN_B];

// ---------------- helpers ----------------
__device__ __forceinline__ void split2h(float v, __half& hi, __half& lo) {
    hi = __float2half(v);
    lo = __float2half(v - __half2float(hi));
}
__device__ __forceinline__ float sigf(float z) { return 1.0f / (1.0f + __expf(-z)); }
__device__ __forceinline__ uint32_t smem_u32(const void* p) {
    uint32_t a;
    asm("{ .reg .u64 t; cvta.to.shared.u64 t, %1; cvt.u32.u64 %0, t; }" : "=r"(a) : "l"(p));
    return a;
}
__device__ __forceinline__ void cpa(uint32_t d, const void* s, int srcsz) {
    asm volatile("cp.async.cg.shared.global [%0], [%1], 16, %2;"
                 :: "r"(d), "l"(s), "r"(srcsz) : "memory");
}
#define CP_COMMIT() asm volatile("cp.async.commit_group;" ::: "memory")
#define CP_WAIT2()  asm volatile("cp.async.wait_group 2;" ::: "memory")
#define CP_WAIT0()  asm volatile("cp.async.wait_group 0;" ::: "memory")

// ---------------- weight prep ----------------
__global__ void build_BT(const float* __restrict__ comp, const float* __restrict__ basis,
                         const float* __restrict__ root) {
    int idx = blockIdx.x * blockDim.x + threadIdx.x;
    if (idx >= 128 * NK) return;
    int n = idx / NK, k = idx % NK;
    float w;
    if (k < 1024) {
        int r = k >> 7, i = k & 127;
        float s = 0.0f;
        #pragma unroll
        for (int b = 0; b < NBASIS; b++)
            s += comp[r * NBASIS + b] * basis[(b * 128 + i) * 128 + n];
        w = s;
    } else {
        w = root[(k - 1024) * 128 + n];
    }
    d_Bh[idx] = __float2half(w);
}

__global__ void pack_CT(const float* wk, const float* bk, const float* wq, const float* bq,
                        const float* wv, const float* bv, const float* ws, const float* bs) {
    int idx = blockIdx.x * blockDim.x + threadIdx.x;
    if (idx >= 512 * 128) return;
    int n = idx >> 7, k = idx & 127;
    int sel = n >> 7, cc = n & 127;
    const float* W = (sel == 0) ? wk : (sel == 1) ? wq : (sel == 2) ? wv : ws;
    d_Ch[idx] = __float2half(W[k * 128 + cc]);
    if (k == 0) {
        const float* B = (sel == 0) ? bk : (sel == 1) ? bq : (sel == 2) ? bv : bs;
        d_bcat[n] = B[cc];
    }
}

// ---------------- CSR build ----------------
__global__ void zero_cnt() {
    int i = blockIdx.x * blockDim.x + threadIdx.x;
    if (i < RN) d_cnt[i] = 0;
}
__global__ void count_edges(const int* __restrict__ ei, const int* __restrict__ etype) {
    int e = blockIdx.x * blockDim.x + threadIdx.x;
    if (e >= NEDGES) return;
    atomicAdd(&d_cnt[ei[NEDGES + e] * NREL + etype[e]], 1);
}
__global__ void scan_blocksum() {
    __shared__ int s[SCAN_B];
    int tid = threadIdx.x, gid = blockIdx.x * SCAN_B + tid;
    s[tid] = (gid < RN) ? d_cnt[gid] : 0;
    __syncthreads();
    for (int o = SCAN_B / 2; o > 0; o >>= 1) { if (tid < o) s[tid] += s[tid + o]; __syncthreads(); }
    if (tid == 0) d_part[blockIdx.x] = s[0];
}
__global__ void scan_partials() {
    __shared__ int s[SCAN_B];
    int tid = threadIdx.x;
    int v = (tid < NSCAN) ? d_part[tid] : 0;
    s[tid] = v; __syncthreads();
    for (int o = 1; o < SCAN_B; o <<= 1) {
        int t = (tid >= o) ? s[tid - o] : 0; __syncthreads();
        s[tid] += t; __syncthreads();
    }
    d_ppre[tid] = s[tid] - v;
}
__global__ void scan_final() {
    __shared__ int s[SCAN_B];
    int tid = threadIdx.x, gid = blockIdx.x * SCAN_B + tid;
    int v = (gid < RN) ? d_cnt[gid] : 0;
    s[tid] = v; __syncthreads();
    for (int o = 1; o < SCAN_B; o <<= 1) {
        int t = (tid >= o) ? s[tid - o] : 0; __syncthreads();
        s[tid] += t; __syncthreads();
    }
    int ex = s[tid] - v + d_ppre[blockIdx.x];
    if (gid < RN) {
        d_off[gid] = ex; d_cur[gid] = ex;
        if (gid == RN - 1) d_off[RN] = ex + v;
    }
}
__global__ void scatter_edges(const int* __restrict__ ei, const int* __restrict__ etype) {
    int e = blockIdx.x * blockDim.x + threadIdx.x;
    if (e >= NEDGES) return;
    int pos = atomicAdd(&d_cur[ei[NEDGES + e] * NREL + etype[e]], 1);
    d_ssrc[pos] = ei[e];
}

// ---------------- gather ----------------
__global__ void agg_split(const float* __restrict__ x) {
    int seg = blockIdx.x * 8 + (threadIdx.x >> 5);
    if (seg >= RN) return;
    int lane = threadIdx.x & 31;
    int beg = d_off[seg], end = d_off[seg + 1];
    int dst = seg >> 3, r = seg & 7;
    const float4* x4 = reinterpret_cast<const float4*>(x);
    float4 acc = make_float4(0.f, 0.f, 0.f, 0.f);
    for (int e = beg; e < end; e++) {
        float4 v = __ldg(&x4[(size_t)d_ssrc[e] * 32 + lane]);
        acc.x += v.x; acc.y += v.y; acc.z += v.z; acc.w += v.w;
    }
    float inv = (end > beg) ? 1.0f / (float)(end - beg) : 0.0f;
    float vv[4] = { acc.x * inv, acc.y * inv, acc.z * inv, acc.w * inv };
    __align__(8) __half hi[4], lo[4];
    #pragma unroll
    for (int j = 0; j < 4; j++) split2h(vv[j], hi[j], lo[j]);
    size_t b = (size_t)dst * NK + r * 128 + lane * 4;
    *(uint2*)&d_Ahi[b] = *(uint2*)hi;
    *(uint2*)&d_Alo[b] = *(uint2*)lo;
}

__global__ void xsplit(const float* __restrict__ x) {
    int idx = blockIdx.x * blockDim.x + threadIdx.x;
    if (idx >= NNODES * 32) return;
    int row = idx >> 5, l = idx & 31;
    float4 v = reinterpret_cast<const float4*>(x)[(size_t)row * 32 + l];
    float vv[4] = { v.x, v.y, v.z, v.w };
    __align__(8) __half hi[4], lo[4];
    #pragma unroll
    for (int j = 0; j < 4; j++) split2h(vv[j], hi[j], lo[j]);
    size_t b = (size_t)row * NK + 1024 + l * 4;
    *(uint2*)&d_Ahi[b] = *(uint2*)hi;
    *(uint2*)&d_Alo[b] = *(uint2*)lo;
}

// ---------------- wmma GEMMs: M256 tile, warp 64x64, 1 CTA/SM, 3-stage ----------------
typedef wmma::fragment<wmma::matrix_a, 16, 16, 16, __half, wmma::row_major> FragA;
typedef wmma::fragment<wmma::matrix_b, 16, 16, 16, __half, wmma::col_major> FragB;
typedef wmma::fragment<wmma::accumulator, 16, 16, 16, float> FragC;

// stage (bytes): A_hi[256*40*2=20480] | A_lo[20480] | B[128*40*2=10240] = 51200
#define STAGE_B 51200
#define NSTG    3
#define GSMEM   (NSTG * STAGE_B)     // 153600; gemm2 epilogue 256*132*4=135168 fits

__device__ __forceinline__ void mma_block(char* sm, int st, int wm, int wn, FragC acc[4][4]) {
    __half* p = (__half*)(sm + st * STAGE_B);
    #pragma unroll
    for (int kk = 0; kk < 32; kk += 16) {
        FragA fah[4], fal[4];
        #pragma unroll
        for (int i = 0; i < 4; i++) {
            wmma::load_matrix_sync(fah[i], p + (wm + i * 16) * 40 + kk, 40);
            wmma::load_matrix_sync(fal[i], p + 10240 + (wm + i * 16) * 40 + kk, 40);
        }
        #pragma unroll
        for (int j = 0; j < 4; j++) {
            FragB fb;
            wmma::load_matrix_sync(fb, p + 20480 + (wn + j * 16) * 40 + kk, 40);
            #pragma unroll
            for (int i = 0; i < 4; i++) {
                wmma::mma_sync(acc[i][j], fah[i], fb, acc[i][j]);
                wmma::mma_sync(acc[i][j], fal[i], fb, acc[i][j]);
            }
        }
    }
}

// GEMM1 split-K: blockIdx.y = kz in [0,3), chunks [kz*12, kz*12+12); partials -> d_P
__global__ void __launch_bounds__(256, 1) gemm1_wmma() {
    extern __shared__ __align__(16) char sm[];
    uint32_t sa = smem_u32(sm);
    int tid = threadIdx.x, wid = tid >> 5;
    int m0 = blockIdx.x << 8;
    int kz = blockIdx.y;
    int wm = (wid & 3) << 6;
    int wn = (wid >> 2) << 6;

    FragC acc[4][4];
    #pragma unroll
    for (int i = 0; i < 4; i++)
        #pragma unroll
        for (int j = 0; j < 4; j++) wmma::fill_fragment(acc[i][j], 0.0f);

    int kbase = kz * (KCH * 32);
    auto issue = [&](int ch, int st) {
        int k0 = kbase + (ch << 5);
        uint32_t so = sa + st * STAGE_B;
        #pragma unroll
        for (int t = tid; t < 1024; t += 256) {
            int row = t >> 2, c8 = (t & 3) << 3;
            int gr = m0 + row;
            int pr = (gr < NNODES) ? 16 : 0;
            int grc = (gr < NNODES) ? gr : 0;
            size_t ga = (size_t)grc * NK + k0 + c8;
            uint32_t ds = so + row * 80 + c8 * 2;
            cpa(ds,         d_Ahi + ga, pr);
            cpa(ds + 20480, d_Alo + ga, pr);
        }
        #pragma unroll
        for (int t = tid; t < 512; t += 256) {
            int row = t >> 2, c8 = (t & 3) << 3;
            size_t gb = (size_t)row * NK + k0 + c8;
            cpa(so + 40960 + row * 80 + c8 * 2, d_Bh + gb, 16);
        }
    };

    issue(0, 0); CP_COMMIT();
    issue(1, 1); CP_COMMIT();
    for (int ch = 0; ch < KCH; ch++) {
        if (ch + 2 < KCH) issue(ch + 2, (ch + 2) % NSTG);
        CP_COMMIT();
        CP_WAIT2();
        __syncthreads();
        mma_block(sm, ch % NSTG, wm, wn, acc);
        __syncthreads();
    }
    CP_WAIT0();

    float* P = d_P + (size_t)kz * MPAD * 128;
    #pragma unroll
    for (int i = 0; i < 4; i++)
        #pragma unroll
        for (int j = 0; j < 4; j++)
            wmma::store_matrix_sync(&P[(size_t)(m0 + wm + i * 16) * 128 + wn + j * 16],
                                    acc[i][j], 128, wmma::mem_row_major);
}

// h = P0 + P1 + P2 + bias1 -> split fp16
__global__ void finish_h(const float* __restrict__ bias1) {
    int idx = blockIdx.x * blockDim.x + threadIdx.x;
    if (idx >= NNODES * 32) return;
    int row = idx >> 5, c4 = (idx & 31) << 2;
    size_t o = (size_t)row * 128 + c4;
    float4 a = *(const float4*)&d_P[o];
    float4 b = *(const float4*)&d_P[(size_t)MPAD * 128 + o];
    float4 c = *(const float4*)&d_P[2 * (size_t)MPAD * 128 + o];
    float vv[4] = { a.x + b.x + c.x + bias1[c4],     a.y + b.y + c.y + bias1[c4 + 1],
                    a.z + b.z + c.z + bias1[c4 + 2], a.w + b.w + c.w + bias1[c4 + 3] };
    __align__(8) __half hi[4], lo[4];
    #pragma unroll
    for (int j = 0; j < 4; j++) split2h(vv[j], hi[j], lo[j]);
    *(uint2*)&d_hhi[o] = *(uint2*)hi;
    *(uint2*)&d_hlo[o] = *(uint2*)lo;
}

__global__ void __launch_bounds__(256, 1) gemm2_wmma() {
    extern __shared__ __align__(16) char sm[];
    uint32_t sa = smem_u32(sm);
    int tid = threadIdx.x, wid = tid >> 5;
    int m0 = blockIdx.x << 8;
    int n0 = blockIdx.y << 7;
    int wm = (wid & 3) << 6;
    int wn = (wid >> 2) << 6;

    FragC acc[4][4];
    #pragma unroll
    for (int i = 0; i < 4; i++)
        #pragma unroll
        for (int j = 0; j < 4; j++) wmma::fill_fragment(acc[i][j], 0.0f);

    auto issue = [&](int ch, int st) {
        int k0 = ch << 5;
        uint32_t so = sa + st * STAGE_B;
        #pragma unroll
        for (int t = tid; t < 1024; t += 256) {
            int row = t >> 2, c8 = (t & 3) << 3;
            int gr = m0 + row;
            int pr = (gr < NNODES) ? 16 : 0;
            int grc = (gr < NNODES) ? gr : 0;
            size_t ga = (size_t)grc * 128 + k0 + c8;
            uint32_t ds = so + row * 80 + c8 * 2;
            cpa(ds,         d_hhi + ga, pr);
            cpa(ds + 20480, d_hlo + ga, pr);
        }
        #pragma unroll
        for (int t = tid; t < 512; t += 256) {
            int row = t >> 2, c8 = (t & 3) << 3;
            size_t gb = (size_t)(n0 + row) * 128 + k0 + c8;
            cpa(so + 40960 + row * 80 + c8 * 2, d_Ch + gb, 16);
        }
    };

    issue(0, 0); CP_COMMIT();
    issue(1, 1); CP_COMMIT();
    for (int ch = 0; ch < 4; ch++) {
        if (ch + 2 < 4) issue(ch + 2, (ch + 2) % NSTG);
        CP_COMMIT();
        CP_WAIT2();
        __syncthreads();
        mma_block(sm, ch % NSTG, wm, wn, acc);
        __syncthreads();
    }
    CP_WAIT0();
    __syncthreads();

    float* sC = (float*)sm;
    #pragma unroll
    for (int i = 0; i < 4; i++)
        #pragma unroll
        for (int j = 0; j < 4; j++)
            wmma::store_matrix_sync(&sC[(wm + i * 16) * 132 + wn + j * 16],
                                    acc[i][j], 132, wmma::mem_row_major);
    __syncthreads();
    int sel = n0 >> 7;
    for (int t = tid; t < 8192; t += 256) {
        int row = t >> 5, c4 = (t & 31) << 2;
        int gr = m0 + row;
        if (gr >= NNODES) continue;
        const float* p = &sC[row * 132 + c4];
        int c = n0 + c4;
        float4 v = make_float4(p[0] + d_bcat[c], p[1] + d_bcat[c + 1],
                               p[2] + d_bcat[c + 2], p[3] + d_bcat[c + 3]);
        float* dst;
        if (sel == 0)      dst = &d_kskip[(size_t)gr * 256 + c4];
        else if (sel == 1) dst = &d_qv[(size_t)gr * 256 + c4];
        else if (sel == 2) dst = &d_qv[(size_t)gr * 256 + 128 + c4];
        else               dst = &d_kskip[(size_t)gr * 256 + 128 + c4];
        *(float4*)dst = v;
    }
}

// ---------------- gate ----------------
__global__ void gate_kernel(float* __restrict__ out) {
    int dst = blockIdx.x * 8 + (threadIdx.x >> 5);
    if (dst >= NNODES) return;
    int lane = threadIdx.x & 31;
    const float4* ks4 = reinterpret_cast<const float4*>(d_kskip);
    const float4* qv4 = reinterpret_cast<const float4*>(d_qv);
    float4 kd  = ks4[(size_t)dst * 64 + lane];
    float4 acc = ks4[(size_t)dst * 64 + 32 + lane];
    int beg = d_off[dst * NREL];
    int end = d_off[dst * NREL + NREL];
    for (int e = beg; e < end; e++) {
        int s = d_ssrc[e];
        float4 q = __ldg(&qv4[(size_t)s * 64 + lane]);
        float4 v = __ldg(&qv4[(size_t)s * 64 + 32 + lane]);
        acc.x += v.x * sigf(kd.x + q.x);
        acc.y += v.y * sigf(kd.y + q.y);
        acc.z += v.z * sigf(kd.z + q.z);
        acc.w += v.w * sigf(kd.w + q.w);
    }
    reinterpret_cast<float4*>(out)[(size_t)dst * 32 + lane] = acc;
}

// ---------------- launcher ----------------
extern "C" void kernel_launch(void* const* d_in, const int* in_sizes, int n_in,
                              void* d_out, int out_size) {
    const float* x     = (const float*)d_in[0];
    const int*   ei    = (const int*)  d_in[1];
    const int*   etype = (const int*)  d_in[3];
    const float* basis = (const float*)d_in[4];
    const float* comp  = (const float*)d_in[5];
    const float* root  = (const float*)d_in[6];
    const float* bias1 = (const float*)d_in[7];
    const float* wk = (const float*)d_in[8];  const float* bk = (const float*)d_in[9];
    const float* wq = (const float*)d_in[10]; const float* bq = (const float*)d_in[11];
    const float* wv = (const float*)d_in[12]; const float* bv = (const float*)d_in[13];
    const float* ws = (const float*)d_in[14]; const float* bs = (const float*)d_in[15];
    float* out = (float*)d_out;

    cudaFuncSetAttribute(gemm1_wmma, cudaFuncAttributeMaxDynamicSharedMemorySize, GSMEM);
    cudaFuncSetAttribute(gemm2_wmma, cudaFuncAttributeMaxDynamicSharedMemorySize, GSMEM);

    build_BT<<<(128 * NK + 255) / 256, 256>>>(comp, basis, root);
    pack_CT<<<(512 * 128 + 255) / 256, 256>>>(wk, bk, wq, bq, wv, bv, ws, bs);

    zero_cnt<<<(RN + 255) / 256, 256>>>();
    count_edges<<<(NEDGES + 255) / 256, 256>>>(ei, etype);
    scan_blocksum<<<NSCAN, SCAN_B>>>();
    scan_partials<<<1, SCAN_B>>>();
    scan_final<<<NSCAN, SCAN_B>>>();
    scatter_edges<<<(NEDGES + 255) / 256, 256>>>(ei, etype);

    xsplit<<<(NNODES * 32 + 255) / 256, 256>>>(x);
    agg_split<<<RN / 8, 256>>>(x);

    gemm1_wmma<<<dim3(MT256, KZ), 256, GSMEM>>>();
    finish_h<<<(NNODES * 32 + 255) / 256, 256>>>(bias1);
    gemm2_wmma<<<dim3(MT256, 4), 256, GSMEM>>>();

    gate_kernel<<<(NNODES + 7) / 8, 256>>>(out);
}

// round 8
// speedup vs baseline: 1.1123x; 1.1123x over previous
#include <cuda_runtime.h>
#include <cuda_fp16.h>
#include <mma.h>
#include <cstdint>

using namespace nvcuda;

#define NNODES 50000
#define NEDGES 600000
#define NREL   8
#define NBASIS 32
#define RN     (NREL * NNODES)
#define SCAN_B 1024
#define NSCAN  ((RN + SCAN_B - 1) / SCAN_B)
#define NK     1152
#define MT     ((NNODES + 127) / 128)    // 391
#define MPAD   (MT * 128)                // 50048
#define KZ     3
#define KCH    12                         // 3 * 12 * 32 = 1152

// ---------------- static device scratch ----------------
static __device__ __align__(16) __half d_Ahi[(size_t)NNODES * NK];
static __device__ __align__(16) __half d_Alo[(size_t)NNODES * NK];
static __device__ __align__(16) __half d_Bh[128 * NK];           // [n][k]
static __device__ __align__(16) __half d_Ch[512 * 128];          // [n][k]
static __device__ __align__(16) float d_bcat[512];
static __device__ __align__(16) __half d_hh[(size_t)NNODES * 128];  // plain fp16 h
static __device__ __align__(16) float d_P[KZ * (size_t)MPAD * 128];
static __device__ __align__(16) float d_kskip[(size_t)NNODES * 256];
static __device__ __align__(16) float d_qv[(size_t)NNODES * 256];
static __device__ int d_cnt[RN];
static __device__ int d_off[RN + 1];
static __device__ int d_cur[RN];
static __device__ int d_ssrc[NEDGES];
static __device__ int d_part[SCAN_B];
static __device__ int d_ppre[SCAN_B];

// ---------------- helpers ----------------
__device__ __forceinline__ void split2h(float v, __half& hi, __half& lo) {
    hi = __float2half(v);
    lo = __float2half(v - __half2float(hi));
}
__device__ __forceinline__ float sigf(float z) { return 1.0f / (1.0f + __expf(-z)); }
__device__ __forceinline__ uint32_t smem_u32(const void* p) {
    uint32_t a;
    asm("{ .reg .u64 t; cvta.to.shared.u64 t, %1; cvt.u32.u64 %0, t; }" : "=r"(a) : "l"(p));
    return a;
}
__device__ __forceinline__ void cpa(uint32_t d, const void* s, int srcsz) {
    asm volatile("cp.async.cg.shared.global [%0], [%1], 16, %2;"
                 :: "r"(d), "l"(s), "r"(srcsz) : "memory");
}
#define CP_COMMIT() asm volatile("cp.async.commit_group;" ::: "memory")
#define CP_WAIT2()  asm volatile("cp.async.wait_group 2;" ::: "memory")
#define CP_WAIT0()  asm volatile("cp.async.wait_group 0;" ::: "memory")

// ---------------- weight prep ----------------
__global__ void build_BT(const float* __restrict__ comp, const float* __restrict__ basis,
                         const float* __restrict__ root) {
    int idx = blockIdx.x * blockDim.x + threadIdx.x;
    if (idx >= 128 * NK) return;
    int n = idx / NK, k = idx % NK;
    float w;
    if (k < 1024) {
        int r = k >> 7, i = k & 127;
        float s = 0.0f;
        #pragma unroll
        for (int b = 0; b < NBASIS; b++)
            s += comp[r * NBASIS + b] * basis[(b * 128 + i) * 128 + n];
        w = s;
    } else {
        w = root[(k - 1024) * 128 + n];
    }
    d_Bh[idx] = __float2half(w);
}

__global__ void pack_CT(const float* wk, const float* bk, const float* wq, const float* bq,
                        const float* wv, const float* bv, const float* ws, const float* bs) {
    int idx = blockIdx.x * blockDim.x + threadIdx.x;
    if (idx >= 512 * 128) return;
    int n = idx >> 7, k = idx & 127;
    int sel = n >> 7, cc = n & 127;
    const float* W = (sel == 0) ? wk : (sel == 1) ? wq : (sel == 2) ? wv : ws;
    d_Ch[idx] = __float2half(W[k * 128 + cc]);
    if (k == 0) {
        const float* B = (sel == 0) ? bk : (sel == 1) ? bq : (sel == 2) ? bv : bs;
        d_bcat[n] = B[cc];
    }
}

// ---------------- CSR build ----------------
__global__ void zero_cnt() {
    int i = blockIdx.x * blockDim.x + threadIdx.x;
    if (i < RN) d_cnt[i] = 0;
}
__global__ void count_edges(const int* __restrict__ ei, const int* __restrict__ etype) {
    int e = blockIdx.x * blockDim.x + threadIdx.x;
    if (e >= NEDGES) return;
    atomicAdd(&d_cnt[ei[NEDGES + e] * NREL + etype[e]], 1);
}
__global__ void scan_blocksum() {
    __shared__ int s[SCAN_B];
    int tid = threadIdx.x, gid = blockIdx.x * SCAN_B + tid;
    s[tid] = (gid < RN) ? d_cnt[gid] : 0;
    __syncthreads();
    for (int o = SCAN_B / 2; o > 0; o >>= 1) { if (tid < o) s[tid] += s[tid + o]; __syncthreads(); }
    if (tid == 0) d_part[blockIdx.x] = s[0];
}
__global__ void scan_partials() {
    __shared__ int s[SCAN_B];
    int tid = threadIdx.x;
    int v = (tid < NSCAN) ? d_part[tid] : 0;
    s[tid] = v; __syncthreads();
    for (int o = 1; o < SCAN_B; o <<= 1) {
        int t = (tid >= o) ? s[tid - o] : 0; __syncthreads();
        s[tid] += t; __syncthreads();
    }
    d_ppre[tid] = s[tid] - v;
}
__global__ void scan_final() {
    __shared__ int s[SCAN_B];
    int tid = threadIdx.x, gid = blockIdx.x * SCAN_B + tid;
    int v = (gid < RN) ? d_cnt[gid] : 0;
    s[tid] = v; __syncthreads();
    for (int o = 1; o < SCAN_B; o <<= 1) {
        int t = (tid >= o) ? s[tid - o] : 0; __syncthreads();
        s[tid] += t; __syncthreads();
    }
    int ex = s[tid] - v + d_ppre[blockIdx.x];
    if (gid < RN) {
        d_off[gid] = ex; d_cur[gid] = ex;
        if (gid == RN - 1) d_off[RN] = ex + v;
    }
}
__global__ void scatter_edges(const int* __restrict__ ei, const int* __restrict__ etype) {
    int e = blockIdx.x * blockDim.x + threadIdx.x;
    if (e >= NEDGES) return;
    int pos = atomicAdd(&d_cur[ei[NEDGES + e] * NREL + etype[e]], 1);
    d_ssrc[pos] = ei[e];
}

// ---------------- gather ----------------
__global__ void agg_split(const float* __restrict__ x) {
    int seg = blockIdx.x * 8 + (threadIdx.x >> 5);
    if (seg >= RN) return;
    int lane = threadIdx.x & 31;
    int beg = d_off[seg], end = d_off[seg + 1];
    int dst = seg >> 3, r = seg & 7;
    const float4* x4 = reinterpret_cast<const float4*>(x);
    float4 acc = make_float4(0.f, 0.f, 0.f, 0.f);
    for (int e = beg; e < end; e++) {
        float4 v = __ldg(&x4[(size_t)d_ssrc[e] * 32 + lane]);
        acc.x += v.x; acc.y += v.y; acc.z += v.z; acc.w += v.w;
    }
    float inv = (end > beg) ? 1.0f / (float)(end - beg) : 0.0f;
    float vv[4] = { acc.x * inv, acc.y * inv, acc.z * inv, acc.w * inv };
    __align__(8) __half hi[4], lo[4];
    #pragma unroll
    for (int j = 0; j < 4; j++) split2h(vv[j], hi[j], lo[j]);
    size_t b = (size_t)dst * NK + r * 128 + lane * 4;
    *(uint2*)&d_Ahi[b] = *(uint2*)hi;
    *(uint2*)&d_Alo[b] = *(uint2*)lo;
}

__global__ void xsplit(const float* __restrict__ x) {
    int idx = blockIdx.x * blockDim.x + threadIdx.x;
    if (idx >= NNODES * 32) return;
    int row = idx >> 5, l = idx & 31;
    float4 v = reinterpret_cast<const float4*>(x)[(size_t)row * 32 + l];
    float vv[4] = { v.x, v.y, v.z, v.w };
    __align__(8) __half hi[4], lo[4];
    #pragma unroll
    for (int j = 0; j < 4; j++) split2h(vv[j], hi[j], lo[j]);
    size_t b = (size_t)row * NK + 1024 + l * 4;
    *(uint2*)&d_Ahi[b] = *(uint2*)hi;
    *(uint2*)&d_Alo[b] = *(uint2*)lo;
}

// ---------------- wmma GEMMs ----------------
typedef wmma::fragment<wmma::matrix_a, 16, 16, 16, __half, wmma::row_major> FragA;
typedef wmma::fragment<wmma::matrix_b, 16, 16, 16, __half, wmma::col_major> FragB;
typedef wmma::fragment<wmma::accumulator, 16, 16, 16, float> FragC;

// GEMM1 stage: A_hi[10240] | A_lo[10240] | B[10240] = 30720 B
#define STAGE1_B 30720
#define NSTG     3
#define GSMEM1   (NSTG * STAGE1_B)   // 92160; epilogue not needed (direct P store)
// GEMM2 stage: A[10240] | B[10240] = 20480 B; epilogue buf 128*132*4 = 67584
#define STAGE2_B 20480
#define GSMEM2   67584               // > 3*20480 = 61440

__device__ __forceinline__ void mma_block1(char* sm, int st, int wm, int wn, FragC acc[2][4]) {
    __half* p = (__half*)(sm + st * STAGE1_B);
    #pragma unroll
    for (int kk = 0; kk < 32; kk += 16) {
        FragA fah[2], fal[2];
        #pragma unroll
        for (int i = 0; i < 2; i++) {
            wmma::load_matrix_sync(fah[i], p + (wm + i * 16) * 40 + kk, 40);
            wmma::load_matrix_sync(fal[i], p + 5120 + (wm + i * 16) * 40 + kk, 40);
        }
        #pragma unroll
        for (int j = 0; j < 4; j++) {
            FragB fb;
            wmma::load_matrix_sync(fb, p + 10240 + (wn + j * 16) * 40 + kk, 40);
            #pragma unroll
            for (int i = 0; i < 2; i++) {
                wmma::mma_sync(acc[i][j], fah[i], fb, acc[i][j]);
                wmma::mma_sync(acc[i][j], fal[i], fb, acc[i][j]);
            }
        }
    }
}

__device__ __forceinline__ void mma_block2(char* sm, int st, int wm, int wn, FragC acc[2][4]) {
    __half* p = (__half*)(sm + st * STAGE2_B);
    #pragma unroll
    for (int kk = 0; kk < 32; kk += 16) {
        FragA fa[2];
        #pragma unroll
        for (int i = 0; i < 2; i++)
            wmma::load_matrix_sync(fa[i], p + (wm + i * 16) * 40 + kk, 40);
        #pragma unroll
        for (int j = 0; j < 4; j++) {
            FragB fb;
            wmma::load_matrix_sync(fb, p + 5120 + (wn + j * 16) * 40 + kk, 40);
            #pragma unroll
            for (int i = 0; i < 2; i++)
                wmma::mma_sync(acc[i][j], fa[i], fb, acc[i][j]);
        }
    }
}

// GEMM1 split-K=3: blockIdx.y = kz, chunks [kz*12, kz*12+12); partials -> d_P
__global__ void __launch_bounds__(256, 2) gemm1_wmma() {
    extern __shared__ __align__(16) char sm[];
    uint32_t sa = smem_u32(sm);
    int tid = threadIdx.x, wid = tid >> 5;
    int m0 = blockIdx.x << 7;
    int kz = blockIdx.y;
    int wm = (wid & 3) << 5;
    int wn = (wid >> 2) << 6;

    FragC acc[2][4];
    #pragma unroll
    for (int i = 0; i < 2; i++)
        #pragma unroll
        for (int j = 0; j < 4; j++) wmma::fill_fragment(acc[i][j], 0.0f);

    int kbase = kz * (KCH * 32);
    auto issue = [&](int ch, int st) {
        int k0 = kbase + (ch << 5);
        uint32_t so = sa + st * STAGE1_B;
        #pragma unroll
        for (int t = tid; t < 512; t += 256) {
            int row = t >> 2, c8 = (t & 3) << 3;
            int gr = m0 + row;
            int pr = (gr < NNODES) ? 16 : 0;
            int grc = (gr < NNODES) ? gr : 0;
            size_t ga = (size_t)grc * NK + k0 + c8;
            uint32_t ds = so + row * 80 + c8 * 2;
            cpa(ds,         d_Ahi + ga, pr);
            cpa(ds + 10240, d_Alo + ga, pr);
            size_t gb = (size_t)row * NK + k0 + c8;
            cpa(ds + 20480, d_Bh + gb, 16);
        }
    };

    issue(0, 0); CP_COMMIT();
    issue(1, 1); CP_COMMIT();
    for (int ch = 0; ch < KCH; ch++) {
        if (ch + 2 < KCH) issue(ch + 2, (ch + 2) % NSTG);
        CP_COMMIT();
        CP_WAIT2();
        __syncthreads();
        mma_block1(sm, ch % NSTG, wm, wn, acc);
        __syncthreads();
    }
    CP_WAIT0();

    float* P = d_P + (size_t)kz * MPAD * 128;
    #pragma unroll
    for (int i = 0; i < 2; i++)
        #pragma unroll
        for (int j = 0; j < 4; j++)
            wmma::store_matrix_sync(&P[(size_t)(m0 + wm + i * 16) * 128 + wn + j * 16],
                                    acc[i][j], 128, wmma::mem_row_major);
}

// h = P0 + P1 + P2 + bias1 -> plain fp16
__global__ void finish_h(const float* __restrict__ bias1) {
    int idx = blockIdx.x * blockDim.x + threadIdx.x;
    if (idx >= NNODES * 32) return;
    int row = idx >> 5, c4 = (idx & 31) << 2;
    size_t o = (size_t)row * 128 + c4;
    float4 a = *(const float4*)&d_P[o];
    float4 b = *(const float4*)&d_P[(size_t)MPAD * 128 + o];
    float4 c = *(const float4*)&d_P[2 * (size_t)MPAD * 128 + o];
    __align__(8) __half hv[4];
    hv[0] = __float2half(a.x + b.x + c.x + bias1[c4]);
    hv[1] = __float2half(a.y + b.y + c.y + bias1[c4 + 1]);
    hv[2] = __float2half(a.z + b.z + c.z + bias1[c4 + 2]);
    hv[3] = __float2half(a.w + b.w + c.w + bias1[c4 + 3]);
    *(uint2*)&d_hh[o] = *(uint2*)hv;
}

__global__ void __launch_bounds__(256, 2) gemm2_wmma() {
    extern __shared__ __align__(16) char sm[];
    uint32_t sa = smem_u32(sm);
    int tid = threadIdx.x, wid = tid >> 5;
    int m0 = blockIdx.x << 7;
    int n0 = blockIdx.y << 7;
    int wm = (wid & 3) << 5;
    int wn = (wid >> 2) << 6;

    FragC acc[2][4];
    #pragma unroll
    for (int i = 0; i < 2; i++)
        #pragma unroll
        for (int j = 0; j < 4; j++) wmma::fill_fragment(acc[i][j], 0.0f);

    auto issue = [&](int ch, int st) {
        int k0 = ch << 5;
        uint32_t so = sa + st * STAGE2_B;
        #pragma unroll
        for (int t = tid; t < 512; t += 256) {
            int row = t >> 2, c8 = (t & 3) << 3;
            int gr = m0 + row;
            int pr = (gr < NNODES) ? 16 : 0;
            int grc = (gr < NNODES) ? gr : 0;
            size_t ga = (size_t)grc * 128 + k0 + c8;
            uint32_t ds = so + row * 80 + c8 * 2;
            cpa(ds, d_hh + ga, pr);
            size_t gb = (size_t)(n0 + row) * 128 + k0 + c8;
            cpa(ds + 10240, d_Ch + gb, 16);
        }
    };

    issue(0, 0); CP_COMMIT();
    issue(1, 1); CP_COMMIT();
    for (int ch = 0; ch < 4; ch++) {
        if (ch + 2 < 4) issue(ch + 2, (ch + 2) % NSTG);
        CP_COMMIT();
        CP_WAIT2();
        __syncthreads();
        mma_block2(sm, ch % NSTG, wm, wn, acc);
        __syncthreads();
    }
    CP_WAIT0();
    __syncthreads();

    float* sC = (float*)sm;
    #pragma unroll
    for (int i = 0; i < 2; i++)
        #pragma unroll
        for (int j = 0; j < 4; j++)
            wmma::store_matrix_sync(&sC[(wm + i * 16) * 132 + wn + j * 16],
                                    acc[i][j], 132, wmma::mem_row_major);
    __syncthreads();
    int sel = n0 >> 7;
    for (int t = tid; t < 4096; t += 256) {
        int row = t >> 5, c4 = (t & 31) << 2;
        int gr = m0 + row;
        if (gr >= NNODES) continue;
        const float* p = &sC[row * 132 + c4];
        int c = n0 + c4;
        float4 v = make_float4(p[0] + d_bcat[c], p[1] + d_bcat[c + 1],
                               p[2] + d_bcat[c + 2], p[3] + d_bcat[c + 3]);
        float* dst;
        if (sel == 0)      dst = &d_kskip[(size_t)gr * 256 + c4];
        else if (sel == 1) dst = &d_qv[(size_t)gr * 256 + c4];
        else if (sel == 2) dst = &d_qv[(size_t)gr * 256 + 128 + c4];
        else               dst = &d_kskip[(size_t)gr * 256 + 128 + c4];
        *(float4*)dst = v;
    }
}

// ---------------- gate ----------------
__global__ void gate_kernel(float* __restrict__ out) {
    int dst = blockIdx.x * 8 + (threadIdx.x >> 5);
    if (dst >= NNODES) return;
    int lane = threadIdx.x & 31;
    const float4* ks4 = reinterpret_cast<const float4*>(d_kskip);
    const float4* qv4 = reinterpret_cast<const float4*>(d_qv);
    float4 kd  = ks4[(size_t)dst * 64 + lane];
    float4 acc = ks4[(size_t)dst * 64 + 32 + lane];
    int beg = d_off[dst * NREL];
    int end = d_off[dst * NREL + NREL];
    for (int e = beg; e < end; e++) {
        int s = d_ssrc[e];
        float4 q = __ldg(&qv4[(size_t)s * 64 + lane]);
        float4 v = __ldg(&qv4[(size_t)s * 64 + 32 + lane]);
        acc.x += v.x * sigf(kd.x + q.x);
        acc.y += v.y * sigf(kd.y + q.y);
        acc.z += v.z * sigf(kd.z + q.z);
        acc.w += v.w * sigf(kd.w + q.w);
    }
    reinterpret_cast<float4*>(out)[(size_t)dst * 32 + lane] = acc;
}

// ---------------- launcher ----------------
extern "C" void kernel_launch(void* const* d_in, const int* in_sizes, int n_in,
                              void* d_out, int out_size) {
    const float* x     = (const float*)d_in[0];
    const int*   ei    = (const int*)  d_in[1];
    const int*   etype = (const int*)  d_in[3];
    const float* basis = (const float*)d_in[4];
    const float* comp  = (const float*)d_in[5];
    const float* root  = (const float*)d_in[6];
    const float* bias1 = (const float*)d_in[7];
    const float* wk = (const float*)d_in[8];  const float* bk = (const float*)d_in[9];
    const float* wq = (const float*)d_in[10]; const float* bq = (const float*)d_in[11];
    const float* wv = (const float*)d_in[12]; const float* bv = (const float*)d_in[13];
    const float* ws = (const float*)d_in[14]; const float* bs = (const float*)d_in[15];
    float* out = (float*)d_out;

    cudaFuncSetAttribute(gemm1_wmma, cudaFuncAttributeMaxDynamicSharedMemorySize, GSMEM1);
    cudaFuncSetAttribute(gemm2_wmma, cudaFuncAttributeMaxDynamicSharedMemorySize, GSMEM2);

    build_BT<<<(128 * NK + 255) / 256, 256>>>(comp, basis, root);
    pack_CT<<<(512 * 128 + 255) / 256, 256>>>(wk, bk, wq, bq, wv, bv, ws, bs);

    zero_cnt<<<(RN + 255) / 256, 256>>>();
    count_edges<<<(NEDGES + 255) / 256, 256>>>(ei, etype);
    scan_blocksum<<<NSCAN, SCAN_B>>>();
    scan_partials<<<1, SCAN_B>>>();
    scan_final<<<NSCAN, SCAN_B>>>();
    scatter_edges<<<(NEDGES + 255) / 256, 256>>>(ei, etype);

    xsplit<<<(NNODES * 32 + 255) / 256, 256>>>(x);
    agg_split<<<RN / 8, 256>>>(x);

    gemm1_wmma<<<dim3(MT, KZ), 256, GSMEM1>>>();
    finish_h<<<(NNODES * 32 + 255) / 256, 256>>>(bias1);
    gemm2_wmma<<<dim3(MT, 4), 256, GSMEM2>>>();

    gate_kernel<<<(NNODES + 7) / 8, 256>>>(out);
}

// round 9
// speedup vs baseline: 1.2865x; 1.1566x over previous
#include <cuda_runtime.h>
#include <cuda_fp16.h>
#include <mma.h>
#include <cstdint>

using namespace nvcuda;

#define NNODES 50000
#define NEDGES 600000
#define NREL   8
#define NBASIS 32
#define RN     (NREL * NNODES)
#define SCAN_B 1024
#define NSCAN  ((RN + SCAN_B - 1) / SCAN_B)
#define NK     1152
#define MT     ((NNODES + 127) / 128)    // 391
#define MPAD   (MT * 128)                // 50048
#define KZ     3
#define KCH    12                         // 3 * 12 * 32 = 1152

// ---------------- static device scratch ----------------
static __device__ __align__(16) __half d_Ah[(size_t)NNODES * NK];   // plain fp16 A
static __device__ __align__(16) __half d_Bh[128 * NK];              // [n][k]
static __device__ __align__(16) __half d_Ch[512 * 128];             // [n][k]
static __device__ __align__(16) float d_bcat[512];
static __device__ __align__(16) __half d_hh[(size_t)NNODES * 128];  // plain fp16 h
static __device__ __align__(16) float d_P[KZ * (size_t)MPAD * 128];
static __device__ __align__(16) float d_kskip[(size_t)NNODES * 256];
static __device__ __align__(16) float d_qv[(size_t)NNODES * 256];
static __device__ int d_cnt[RN];
static __device__ int d_off[RN + 1];
static __device__ int d_cur[RN];
static __device__ int d_ssrc[NEDGES];
static __device__ int d_part[SCAN_B];
static __device__ int d_ppre[SCAN_B];

// ---------------- helpers ----------------
__device__ __forceinline__ float sigf(float z) { return 1.0f / (1.0f + __expf(-z)); }
__device__ __forceinline__ uint32_t smem_u32(const void* p) {
    uint32_t a;
    asm("{ .reg .u64 t; cvta.to.shared.u64 t, %1; cvt.u32.u64 %0, t; }" : "=r"(a) : "l"(p));
    return a;
}
__device__ __forceinline__ void cpa(uint32_t d, const void* s, int srcsz) {
    asm volatile("cp.async.cg.shared.global [%0], [%1], 16, %2;"
                 :: "r"(d), "l"(s), "r"(srcsz) : "memory");
}
#define CP_COMMIT() asm volatile("cp.async.commit_group;" ::: "memory")
#define CP_WAIT2()  asm volatile("cp.async.wait_group 2;" ::: "memory")
#define CP_WAIT0()  asm volatile("cp.async.wait_group 0;" ::: "memory")

// ---------------- weight prep ----------------
__global__ void build_BT(const float* __restrict__ comp, const float* __restrict__ basis,
                         const float* __restrict__ root) {
    int idx = blockIdx.x * blockDim.x + threadIdx.x;
    if (idx >= 128 * NK) return;
    int n = idx / NK, k = idx % NK;
    float w;
    if (k < 1024) {
        int r = k >> 7, i = k & 127;
        float s = 0.0f;
        #pragma unroll
        for (int b = 0; b < NBASIS; b++)
            s += comp[r * NBASIS + b] * basis[(b * 128 + i) * 128 + n];
        w = s;
    } else {
        w = root[(k - 1024) * 128 + n];
    }
    d_Bh[idx] = __float2half(w);
}

__global__ void pack_CT(const float* wk, const float* bk, const float* wq, const float* bq,
                        const float* wv, const float* bv, const float* ws, const float* bs) {
    int idx = blockIdx.x * blockDim.x + threadIdx.x;
    if (idx >= 512 * 128) return;
    int n = idx >> 7, k = idx & 127;
    int sel = n >> 7, cc = n & 127;
    const float* W = (sel == 0) ? wk : (sel == 1) ? wq : (sel == 2) ? wv : ws;
    d_Ch[idx] = __float2half(W[k * 128 + cc]);
    if (k == 0) {
        const float* B = (sel == 0) ? bk : (sel == 1) ? bq : (sel == 2) ? bv : bs;
        d_bcat[n] = B[cc];
    }
}

// ---------------- CSR build ----------------
__global__ void zero_cnt() {
    int i = blockIdx.x * blockDim.x + threadIdx.x;
    if (i < RN) d_cnt[i] = 0;
}
__global__ void count_edges(const int* __restrict__ ei, const int* __restrict__ etype) {
    int e = blockIdx.x * blockDim.x + threadIdx.x;
    if (e >= NEDGES) return;
    atomicAdd(&d_cnt[ei[NEDGES + e] * NREL + etype[e]], 1);
}
__global__ void scan_blocksum() {
    __shared__ int s[SCAN_B];
    int tid = threadIdx.x, gid = blockIdx.x * SCAN_B + tid;
    s[tid] = (gid < RN) ? d_cnt[gid] : 0;
    __syncthreads();
    for (int o = SCAN_B / 2; o > 0; o >>= 1) { if (tid < o) s[tid] += s[tid + o]; __syncthreads(); }
    if (tid == 0) d_part[blockIdx.x] = s[0];
}
__global__ void scan_partials() {
    __shared__ int s[SCAN_B];
    int tid = threadIdx.x;
    int v = (tid < NSCAN) ? d_part[tid] : 0;
    s[tid] = v; __syncthreads();
    for (int o = 1; o < SCAN_B; o <<= 1) {
        int t = (tid >= o) ? s[tid - o] : 0; __syncthreads();
        s[tid] += t; __syncthreads();
    }
    d_ppre[tid] = s[tid] - v;
}
__global__ void scan_final() {
    __shared__ int s[SCAN_B];
    int tid = threadIdx.x, gid = blockIdx.x * SCAN_B + tid;
    int v = (gid < RN) ? d_cnt[gid] : 0;
    s[tid] = v; __syncthreads();
    for (int o = 1; o < SCAN_B; o <<= 1) {
        int t = (tid >= o) ? s[tid - o] : 0; __syncthreads();
        s[tid] += t; __syncthreads();
    }
    int ex = s[tid] - v + d_ppre[blockIdx.x];
    if (gid < RN) {
        d_off[gid] = ex; d_cur[gid] = ex;
        if (gid == RN - 1) d_off[RN] = ex + v;
    }
}
__global__ void scatter_edges(const int* __restrict__ ei, const int* __restrict__ etype) {
    int e = blockIdx.x * blockDim.x + threadIdx.x;
    if (e >= NEDGES) return;
    int pos = atomicAdd(&d_cur[ei[NEDGES + e] * NREL + etype[e]], 1);
    d_ssrc[pos] = ei[e];
}

// ---------------- gather: per-(dst,rel) mean -> fp16 A cols 0..1023 ----------------
__global__ void agg_split(const float* __restrict__ x) {
    int seg = blockIdx.x * 8 + (threadIdx.x >> 5);
    if (seg >= RN) return;
    int lane = threadIdx.x & 31;
    int beg = d_off[seg], end = d_off[seg + 1];
    int dst = seg >> 3, r = seg & 7;
    const float4* x4 = reinterpret_cast<const float4*>(x);
    float4 acc = make_float4(0.f, 0.f, 0.f, 0.f);
    for (int e = beg; e < end; e++) {
        float4 v = __ldg(&x4[(size_t)d_ssrc[e] * 32 + lane]);
        acc.x += v.x; acc.y += v.y; acc.z += v.z; acc.w += v.w;
    }
    float inv = (end > beg) ? 1.0f / (float)(end - beg) : 0.0f;
    __align__(8) __half hv[4];
    hv[0] = __float2half(acc.x * inv);
    hv[1] = __float2half(acc.y * inv);
    hv[2] = __float2half(acc.z * inv);
    hv[3] = __float2half(acc.w * inv);
    *(uint2*)&d_Ah[(size_t)dst * NK + r * 128 + lane * 4] = *(uint2*)hv;
}

// x -> fp16 A cols 1024..1151 (root term)
__global__ void xsplit(const float* __restrict__ x) {
    int idx = blockIdx.x * blockDim.x + threadIdx.x;
    if (idx >= NNODES * 32) return;
    int row = idx >> 5, l = idx & 31;
    float4 v = reinterpret_cast<const float4*>(x)[(size_t)row * 32 + l];
    __align__(8) __half hv[4];
    hv[0] = __float2half(v.x);
    hv[1] = __float2half(v.y);
    hv[2] = __float2half(v.z);
    hv[3] = __float2half(v.w);
    *(uint2*)&d_Ah[(size_t)row * NK + 1024 + l * 4] = *(uint2*)hv;
}

// ---------------- wmma GEMMs (plain fp16 operands) ----------------
typedef wmma::fragment<wmma::matrix_a, 16, 16, 16, __half, wmma::row_major> FragA;
typedef wmma::fragment<wmma::matrix_b, 16, 16, 16, __half, wmma::col_major> FragB;
typedef wmma::fragment<wmma::accumulator, 16, 16, 16, float> FragC;

// stage: A[128*40*2=10240] | B[10240] = 20480 B
#define STAGE_B 20480
#define NSTG    3
#define GSMEM   67584     // >= 3*20480=61440, and holds 128x132 fp32 epilogue

__device__ __forceinline__ void mma_block(char* sm, int st, int wm, int wn, FragC acc[2][4]) {
    __half* p = (__half*)(sm + st * STAGE_B);
    #pragma unroll
    for (int kk = 0; kk < 32; kk += 16) {
        FragA fa[2];
        #pragma unroll
        for (int i = 0; i < 2; i++)
            wmma::load_matrix_sync(fa[i], p + (wm + i * 16) * 40 + kk, 40);
        #pragma unroll
        for (int j = 0; j < 4; j++) {
            FragB fb;
            wmma::load_matrix_sync(fb, p + 5120 + (wn + j * 16) * 40 + kk, 40);
            #pragma unroll
            for (int i = 0; i < 2; i++)
                wmma::mma_sync(acc[i][j], fa[i], fb, acc[i][j]);
        }
    }
}

// GEMM1 split-K=3: blockIdx.y = kz, chunks [kz*12, kz*12+12); partials -> d_P
__global__ void __launch_bounds__(256, 2) gemm1_wmma() {
    extern __shared__ __align__(16) char sm[];
    uint32_t sa = smem_u32(sm);
    int tid = threadIdx.x, wid = tid >> 5;
    int m0 = blockIdx.x << 7;
    int kz = blockIdx.y;
    int wm = (wid & 3) << 5;
    int wn = (wid >> 2) << 6;

    FragC acc[2][4];
    #pragma unroll
    for (int i = 0; i < 2; i++)
        #pragma unroll
        for (int j = 0; j < 4; j++) wmma::fill_fragment(acc[i][j], 0.0f);

    int kbase = kz * (KCH * 32);
    auto issue = [&](int ch, int st) {
        int k0 = kbase + (ch << 5);
        uint32_t so = sa + st * STAGE_B;
        #pragma unroll
        for (int t = tid; t < 512; t += 256) {
            int row = t >> 2, c8 = (t & 3) << 3;
            int gr = m0 + row;
            int pr = (gr < NNODES) ? 16 : 0;
            int grc = (gr < NNODES) ? gr : 0;
            size_t ga = (size_t)grc * NK + k0 + c8;
            uint32_t ds = so + row * 80 + c8 * 2;
            cpa(ds, d_Ah + ga, pr);
            size_t gb = (size_t)row * NK + k0 + c8;
            cpa(ds + 10240, d_Bh + gb, 16);
        }
    };

    issue(0, 0); CP_COMMIT();
    issue(1, 1); CP_COMMIT();
    for (int ch = 0; ch < KCH; ch++) {
        if (ch + 2 < KCH) issue(ch + 2, (ch + 2) % NSTG);
        CP_COMMIT();
        CP_WAIT2();
        __syncthreads();
        mma_block(sm, ch % NSTG, wm, wn, acc);
        __syncthreads();
    }
    CP_WAIT0();

    float* P = d_P + (size_t)kz * MPAD * 128;
    #pragma unroll
    for (int i = 0; i < 2; i++)
        #pragma unroll
        for (int j = 0; j < 4; j++)
            wmma::store_matrix_sync(&P[(size_t)(m0 + wm + i * 16) * 128 + wn + j * 16],
                                    acc[i][j], 128, wmma::mem_row_major);
}

// h = P0 + P1 + P2 + bias1 -> plain fp16
__global__ void finish_h(const float* __restrict__ bias1) {
    int idx = blockIdx.x * blockDim.x + threadIdx.x;
    if (idx >= NNODES * 32) return;
    int row = idx >> 5, c4 = (idx & 31) << 2;
    size_t o = (size_t)row * 128 + c4;
    float4 a = *(const float4*)&d_P[o];
    float4 b = *(const float4*)&d_P[(size_t)MPAD * 128 + o];
    float4 c = *(const float4*)&d_P[2 * (size_t)MPAD * 128 + o];
    __align__(8) __half hv[4];
    hv[0] = __float2half(a.x + b.x + c.x + bias1[c4]);
    hv[1] = __float2half(a.y + b.y + c.y + bias1[c4 + 1]);
    hv[2] = __float2half(a.z + b.z + c.z + bias1[c4 + 2]);
    hv[3] = __float2half(a.w + b.w + c.w + bias1[c4 + 3]);
    *(uint2*)&d_hh[o] = *(uint2*)hv;
}

__global__ void __launch_bounds__(256, 2) gemm2_wmma() {
    extern __shared__ __align__(16) char sm[];
    uint32_t sa = smem_u32(sm);
    int tid = threadIdx.x, wid = tid >> 5;
    int m0 = blockIdx.x << 7;
    int n0 = blockIdx.y << 7;
    int wm = (wid & 3) << 5;
    int wn = (wid >> 2) << 6;

    FragC acc[2][4];
    #pragma unroll
    for (int i = 0; i < 2; i++)
        #pragma unroll
        for (int j = 0; j < 4; j++) wmma::fill_fragment(acc[i][j], 0.0f);

    auto issue = [&](int ch, int st) {
        int k0 = ch << 5;
        uint32_t so = sa + st * STAGE_B;
        #pragma unroll
        for (int t = tid; t < 512; t += 256) {
            int row = t >> 2, c8 = (t & 3) << 3;
            int gr = m0 + row;
            int pr = (gr < NNODES) ? 16 : 0;
            int grc = (gr < NNODES) ? gr : 0;
            size_t ga = (size_t)grc * 128 + k0 + c8;
            uint32_t ds = so + row * 80 + c8 * 2;
            cpa(ds, d_hh + ga, pr);
            size_t gb = (size_t)(n0 + row) * 128 + k0 + c8;
            cpa(ds + 10240, d_Ch + gb, 16);
        }
    };

    issue(0, 0); CP_COMMIT();
    issue(1, 1); CP_COMMIT();
    for (int ch = 0; ch < 4; ch++) {
        if (ch + 2 < 4) issue(ch + 2, (ch + 2) % NSTG);
        CP_COMMIT();
        CP_WAIT2();
        __syncthreads();
        mma_block(sm, ch % NSTG, wm, wn, acc);
        __syncthreads();
    }
    CP_WAIT0();
    __syncthreads();

    float* sC = (float*)sm;
    #pragma unroll
    for (int i = 0; i < 2; i++)
        #pragma unroll
        for (int j = 0; j < 4; j++)
            wmma::store_matrix_sync(&sC[(wm + i * 16) * 132 + wn + j * 16],
                                    acc[i][j], 132, wmma::mem_row_major);
    __syncthreads();
    int sel = n0 >> 7;
    for (int t = tid; t < 4096; t += 256) {
        int row = t >> 5, c4 = (t & 31) << 2;
        int gr = m0 + row;
        if (gr >= NNODES) continue;
        const float* p = &sC[row * 132 + c4];
        int c = n0 + c4;
        float4 v = make_float4(p[0] + d_bcat[c], p[1] + d_bcat[c + 1],
                               p[2] + d_bcat[c + 2], p[3] + d_bcat[c + 3]);
        float* dst;
        if (sel == 0)      dst = &d_kskip[(size_t)gr * 256 + c4];
        else if (sel == 1) dst = &d_qv[(size_t)gr * 256 + c4];
        else if (sel == 2) dst = &d_qv[(size_t)gr * 256 + 128 + c4];
        else               dst = &d_kskip[(size_t)gr * 256 + 128 + c4];
        *(float4*)dst = v;
    }
}

// ---------------- gate ----------------
__global__ void gate_kernel(float* __restrict__ out) {
    int dst = blockIdx.x * 8 + (threadIdx.x >> 5);
    if (dst >= NNODES) return;
    int lane = threadIdx.x & 31;
    const float4* ks4 = reinterpret_cast<const float4*>(d_kskip);
    const float4* qv4 = reinterpret_cast<const float4*>(d_qv);
    float4 kd  = ks4[(size_t)dst * 64 + lane];
    float4 acc = ks4[(size_t)dst * 64 + 32 + lane];
    int beg = d_off[dst * NREL];
    int end = d_off[dst * NREL + NREL];
    for (int e = beg; e < end; e++) {
        int s = d_ssrc[e];
        float4 q = __ldg(&qv4[(size_t)s * 64 + lane]);
        float4 v = __ldg(&qv4[(size_t)s * 64 + 32 + lane]);
        acc.x += v.x * sigf(kd.x + q.x);
        acc.y += v.y * sigf(kd.y + q.y);
        acc.z += v.z * sigf(kd.z + q.z);
        acc.w += v.w * sigf(kd.w + q.w);
    }
    reinterpret_cast<float4*>(out)[(size_t)dst * 32 + lane] = acc;
}

// ---------------- launcher ----------------
extern "C" void kernel_launch(void* const* d_in, const int* in_sizes, int n_in,
                              void* d_out, int out_size) {
    const float* x     = (const float*)d_in[0];
    const int*   ei    = (const int*)  d_in[1];
    const int*   etype = (const int*)  d_in[3];
    const float* basis = (const float*)d_in[4];
    const float* comp  = (const float*)d_in[5];
    const float* root  = (const float*)d_in[6];
    const float* bias1 = (const float*)d_in[7];
    const float* wk = (const float*)d_in[8];  const float* bk = (const float*)d_in[9];
    const float* wq = (const float*)d_in[10]; const float* bq = (const float*)d_in[11];
    const float* wv = (const float*)d_in[12]; const float* bv = (const float*)d_in[13];
    const float* ws = (const float*)d_in[14]; const float* bs = (const float*)d_in[15];
    float* out = (float*)d_out;

    cudaFuncSetAttribute(gemm1_wmma, cudaFuncAttributeMaxDynamicSharedMemorySize, GSMEM);
    cudaFuncSetAttribute(gemm2_wmma, cudaFuncAttributeMaxDynamicSharedMemorySize, GSMEM);

    build_BT<<<(128 * NK + 255) / 256, 256>>>(comp, basis, root);
    pack_CT<<<(512 * 128 + 255) / 256, 256>>>(wk, bk, wq, bq, wv, bv, ws, bs);

    zero_cnt<<<(RN + 255) / 256, 256>>>();
    count_edges<<<(NEDGES + 255) / 256, 256>>>(ei, etype);
    scan_blocksum<<<NSCAN, SCAN_B>>>();
    scan_partials<<<1, SCAN_B>>>();
    scan_final<<<NSCAN, SCAN_B>>>();
    scatter_edges<<<(NEDGES + 255) / 256, 256>>>(ei, etype);

    xsplit<<<(NNODES * 32 + 255) / 256, 256>>>(x);
    agg_split<<<RN / 8, 256>>>(x);

    gemm1_wmma<<<dim3(MT, KZ), 256, GSMEM>>>();
    finish_h<<<(NNODES * 32 + 255) / 256, 256>>>(bias1);
    gemm2_wmma<<<dim3(MT, 4), 256, GSMEM>>>();

    gate_kernel<<<(NNODES + 7) / 8, 256>>>(out);
}

// round 10
// speedup vs baseline: 1.3498x; 1.0492x over previous
#include <cuda_runtime.h>
#include <cuda_fp16.h>
#include <mma.h>
#include <cstdint>

using namespace nvcuda;

#define NNODES 50000
#define NEDGES 600000
#define NREL   8
#define NBASIS 32
#define RN     (NREL * NNODES)
#define SCAN_B 1024
#define NSCAN  ((RN + SCAN_B - 1) / SCAN_B)
#define NK     1152
#define MT     ((NNODES + 127) / 128)    // 391
#define MPAD   (MT * 128)                // 50048
#define KZ     3
#define KCH    12                         // 3 * 12 * 32 = 1152

// ---------------- static device scratch ----------------
static __device__ __align__(16) __half d_Ah[(size_t)NNODES * NK];   // fp16 A
static __device__ __align__(16) __half d_Bh[128 * NK];              // [n][k]
static __device__ __align__(16) __half d_Ch[512 * 128];             // [n][k]
static __device__ __align__(16) float d_bcat[512];
static __device__ __align__(16) __half d_hh[(size_t)NNODES * 128];  // fp16 h
static __device__ __align__(16) float d_P[KZ * (size_t)MPAD * 128];
static __device__ __align__(16) float d_kskip[(size_t)NNODES * 256];   // fp32 [k | skip]
static __device__ __align__(16) __half d_qvh[(size_t)NNODES * 256];    // fp16 [q | v]
static __device__ int d_cnt[RN];
static __device__ int d_off[RN + 1];
static __device__ int d_cur[RN];
static __device__ int d_ssrc[NEDGES];
static __device__ int d_part[SCAN_B];
static __device__ int d_ppre[SCAN_B];

// ---------------- helpers ----------------
__device__ __forceinline__ float sigf(float z) { return 1.0f / (1.0f + __expf(-z)); }
__device__ __forceinline__ uint32_t smem_u32(const void* p) {
    uint32_t a;
    asm("{ .reg .u64 t; cvta.to.shared.u64 t, %1; cvt.u32.u64 %0, t; }" : "=r"(a) : "l"(p));
    return a;
}
__device__ __forceinline__ void cpa(uint32_t d, const void* s, int srcsz) {
    asm volatile("cp.async.cg.shared.global [%0], [%1], 16, %2;"
                 :: "r"(d), "l"(s), "r"(srcsz) : "memory");
}
#define CP_COMMIT() asm volatile("cp.async.commit_group;" ::: "memory")
#define CP_WAIT2()  asm volatile("cp.async.wait_group 2;" ::: "memory")
#define CP_WAIT0()  asm volatile("cp.async.wait_group 0;" ::: "memory")

// ---------------- weight prep ----------------
__global__ void build_BT(const float* __restrict__ comp, const float* __restrict__ basis,
                         const float* __restrict__ root) {
    int idx = blockIdx.x * blockDim.x + threadIdx.x;
    if (idx >= 128 * NK) return;
    int n = idx / NK, k = idx % NK;
    float w;
    if (k < 1024) {
        int r = k >> 7, i = k & 127;
        float s = 0.0f;
        #pragma unroll
        for (int b = 0; b < NBASIS; b++)
            s += comp[r * NBASIS + b] * basis[(b * 128 + i) * 128 + n];
        w = s;
    } else {
        w = root[(k - 1024) * 128 + n];
    }
    d_Bh[idx] = __float2half(w);
}

__global__ void pack_CT(const float* wk, const float* bk, const float* wq, const float* bq,
                        const float* wv, const float* bv, const float* ws, const float* bs) {
    int idx = blockIdx.x * blockDim.x + threadIdx.x;
    if (idx >= 512 * 128) return;
    int n = idx >> 7, k = idx & 127;
    int sel = n >> 7, cc = n & 127;
    const float* W = (sel == 0) ? wk : (sel == 1) ? wq : (sel == 2) ? wv : ws;
    d_Ch[idx] = __float2half(W[k * 128 + cc]);
    if (k == 0) {
        const float* B = (sel == 0) ? bk : (sel == 1) ? bq : (sel == 2) ? bv : bs;
        d_bcat[n] = B[cc];
    }
}

// ---------------- CSR build ----------------
__global__ void zero_cnt() {
    int i = blockIdx.x * blockDim.x + threadIdx.x;
    if (i < RN) d_cnt[i] = 0;
}
__global__ void count_edges(const int* __restrict__ ei, const int* __restrict__ etype) {
    int e = blockIdx.x * blockDim.x + threadIdx.x;
    if (e >= NEDGES) return;
    atomicAdd(&d_cnt[ei[NEDGES + e] * NREL + etype[e]], 1);
}
__global__ void scan_blocksum() {
    __shared__ int s[SCAN_B];
    int tid = threadIdx.x, gid = blockIdx.x * SCAN_B + tid;
    s[tid] = (gid < RN) ? d_cnt[gid] : 0;
    __syncthreads();
    for (int o = SCAN_B / 2; o > 0; o >>= 1) { if (tid < o) s[tid] += s[tid + o]; __syncthreads(); }
    if (tid == 0) d_part[blockIdx.x] = s[0];
}
__global__ void scan_partials() {
    __shared__ int s[SCAN_B];
    int tid = threadIdx.x;
    int v = (tid < NSCAN) ? d_part[tid] : 0;
    s[tid] = v; __syncthreads();
    for (int o = 1; o < SCAN_B; o <<= 1) {
        int t = (tid >= o) ? s[tid - o] : 0; __syncthreads();
        s[tid] += t; __syncthreads();
    }
    d_ppre[tid] = s[tid] - v;
}
__global__ void scan_final() {
    __shared__ int s[SCAN_B];
    int tid = threadIdx.x, gid = blockIdx.x * SCAN_B + tid;
    int v = (gid < RN) ? d_cnt[gid] : 0;
    s[tid] = v; __syncthreads();
    for (int o = 1; o < SCAN_B; o <<= 1) {
        int t = (tid >= o) ? s[tid - o] : 0; __syncthreads();
        s[tid] += t; __syncthreads();
    }
    int ex = s[tid] - v + d_ppre[blockIdx.x];
    if (gid < RN) {
        d_off[gid] = ex; d_cur[gid] = ex;
        if (gid == RN - 1) d_off[RN] = ex + v;
    }
}
__global__ void scatter_edges(const int* __restrict__ ei, const int* __restrict__ etype) {
    int e = blockIdx.x * blockDim.x + threadIdx.x;
    if (e >= NEDGES) return;
    int pos = atomicAdd(&d_cur[ei[NEDGES + e] * NREL + etype[e]], 1);
    d_ssrc[pos] = ei[e];
}

// ---------------- gather: per-(dst,rel) mean -> fp16 A cols 0..1023 ----------------
__global__ void agg_split(const float* __restrict__ x) {
    int seg = blockIdx.x * 8 + (threadIdx.x >> 5);
    if (seg >= RN) return;
    int lane = threadIdx.x & 31;
    int beg = d_off[seg], end = d_off[seg + 1];
    int dst = seg >> 3, r = seg & 7;
    const float4* x4 = reinterpret_cast<const float4*>(x);
    float4 acc = make_float4(0.f, 0.f, 0.f, 0.f);
    for (int e = beg; e < end; e++) {
        float4 v = __ldg(&x4[(size_t)d_ssrc[e] * 32 + lane]);
        acc.x += v.x; acc.y += v.y; acc.z += v.z; acc.w += v.w;
    }
    float inv = (end > beg) ? 1.0f / (float)(end - beg) : 0.0f;
    __align__(8) __half hv[4];
    hv[0] = __float2half(acc.x * inv);
    hv[1] = __float2half(acc.y * inv);
    hv[2] = __float2half(acc.z * inv);
    hv[3] = __float2half(acc.w * inv);
    *(uint2*)&d_Ah[(size_t)dst * NK + r * 128 + lane * 4] = *(uint2*)hv;
}

// x -> fp16 A cols 1024..1151 (root term)
__global__ void xsplit(const float* __restrict__ x) {
    int idx = blockIdx.x * blockDim.x + threadIdx.x;
    if (idx >= NNODES * 32) return;
    int row = idx >> 5, l = idx & 31;
    float4 v = reinterpret_cast<const float4*>(x)[(size_t)row * 32 + l];
    __align__(8) __half hv[4];
    hv[0] = __float2half(v.x);
    hv[1] = __float2half(v.y);
    hv[2] = __float2half(v.z);
    hv[3] = __float2half(v.w);
    *(uint2*)&d_Ah[(size_t)row * NK + 1024 + l * 4] = *(uint2*)hv;
}

// ---------------- wmma GEMMs (plain fp16 operands) ----------------
typedef wmma::fragment<wmma::matrix_a, 16, 16, 16, __half, wmma::row_major> FragA;
typedef wmma::fragment<wmma::matrix_b, 16, 16, 16, __half, wmma::col_major> FragB;
typedef wmma::fragment<wmma::accumulator, 16, 16, 16, float> FragC;

// stage: A[128*40*2=10240] | B[10240] = 20480 B
#define STAGE_B 20480
#define NSTG    3
#define GSMEM   67584     // >= 3*20480, holds 128x132 fp32 epilogue

__device__ __forceinline__ void mma_block(char* sm, int st, int wm, int wn, FragC acc[2][4]) {
    __half* p = (__half*)(sm + st * STAGE_B);
    #pragma unroll
    for (int kk = 0; kk < 32; kk += 16) {
        FragA fa[2];
        #pragma unroll
        for (int i = 0; i < 2; i++)
            wmma::load_matrix_sync(fa[i], p + (wm + i * 16) * 40 + kk, 40);
        #pragma unroll
        for (int j = 0; j < 4; j++) {
            FragB fb;
            wmma::load_matrix_sync(fb, p + 5120 + (wn + j * 16) * 40 + kk, 40);
            #pragma unroll
            for (int i = 0; i < 2; i++)
                wmma::mma_sync(acc[i][j], fa[i], fb, acc[i][j]);
        }
    }
}

// GEMM1 split-K=3: blockIdx.y = kz, chunks [kz*12, kz*12+12); partials -> d_P
__global__ void __launch_bounds__(256, 2) gemm1_wmma() {
    extern __shared__ __align__(16) char sm[];
    uint32_t sa = smem_u32(sm);
    int tid = threadIdx.x, wid = tid >> 5;
    int m0 = blockIdx.x << 7;
    int kz = blockIdx.y;
    int wm = (wid & 3) << 5;
    int wn = (wid >> 2) << 6;

    FragC acc[2][4];
    #pragma unroll
    for (int i = 0; i < 2; i++)
        #pragma unroll
        for (int j = 0; j < 4; j++) wmma::fill_fragment(acc[i][j], 0.0f);

    int kbase = kz * (KCH * 32);
    auto issue = [&](int ch, int st) {
        int k0 = kbase + (ch << 5);
        uint32_t so = sa + st * STAGE_B;
        #pragma unroll
        for (int t = tid; t < 512; t += 256) {
            int row = t >> 2, c8 = (t & 3) << 3;
            int gr = m0 + row;
            int pr = (gr < NNODES) ? 16 : 0;
            int grc = (gr < NNODES) ? gr : 0;
            size_t ga = (size_t)grc * NK + k0 + c8;
            uint32_t ds = so + row * 80 + c8 * 2;
            cpa(ds, d_Ah + ga, pr);
            size_t gb = (size_t)row * NK + k0 + c8;
            cpa(ds + 10240, d_Bh + gb, 16);
        }
    };

    issue(0, 0); CP_COMMIT();
    issue(1, 1); CP_COMMIT();
    for (int ch = 0; ch < KCH; ch++) {
        if (ch + 2 < KCH) issue(ch + 2, (ch + 2) % NSTG);
        CP_COMMIT();
        CP_WAIT2();
        __syncthreads();
        mma_block(sm, ch % NSTG, wm, wn, acc);
        __syncthreads();
    }
    CP_WAIT0();

    float* P = d_P + (size_t)kz * MPAD * 128;
    #pragma unroll
    for (int i = 0; i < 2; i++)
        #pragma unroll
        for (int j = 0; j < 4; j++)
            wmma::store_matrix_sync(&P[(size_t)(m0 + wm + i * 16) * 128 + wn + j * 16],
                                    acc[i][j], 128, wmma::mem_row_major);
}

// h = P0 + P1 + P2 + bias1 -> fp16
__global__ void finish_h(const float* __restrict__ bias1) {
    int idx = blockIdx.x * blockDim.x + threadIdx.x;
    if (idx >= NNODES * 32) return;
    int row = idx >> 5, c4 = (idx & 31) << 2;
    size_t o = (size_t)row * 128 + c4;
    float4 a = *(const float4*)&d_P[o];
    float4 b = *(const float4*)&d_P[(size_t)MPAD * 128 + o];
    float4 c = *(const float4*)&d_P[2 * (size_t)MPAD * 128 + o];
    __align__(8) __half hv[4];
    hv[0] = __float2half(a.x + b.x + c.x + bias1[c4]);
    hv[1] = __float2half(a.y + b.y + c.y + bias1[c4 + 1]);
    hv[2] = __float2half(a.z + b.z + c.z + bias1[c4 + 2]);
    hv[3] = __float2half(a.w + b.w + c.w + bias1[c4 + 3]);
    *(uint2*)&d_hh[o] = *(uint2*)hv;
}

__global__ void __launch_bounds__(256, 2) gemm2_wmma() {
    extern __shared__ __align__(16) char sm[];
    uint32_t sa = smem_u32(sm);
    int tid = threadIdx.x, wid = tid >> 5;
    int m0 = blockIdx.x << 7;
    int n0 = blockIdx.y << 7;
    int wm = (wid & 3) << 5;
    int wn = (wid >> 2) << 6;

    FragC acc[2][4];
    #pragma unroll
    for (int i = 0; i < 2; i++)
        #pragma unroll
        for (int j = 0; j < 4; j++) wmma::fill_fragment(acc[i][j], 0.0f);

    auto issue = [&](int ch, int st) {
        int k0 = ch << 5;
        uint32_t so = sa + st * STAGE_B;
        #pragma unroll
        for (int t = tid; t < 512; t += 256) {
            int row = t >> 2, c8 = (t & 3) << 3;
            int gr = m0 + row;
            int pr = (gr < NNODES) ? 16 : 0;
            int grc = (gr < NNODES) ? gr : 0;
            size_t ga = (size_t)grc * 128 + k0 + c8;
            uint32_t ds = so + row * 80 + c8 * 2;
            cpa(ds, d_hh + ga, pr);
            size_t gb = (size_t)(n0 + row) * 128 + k0 + c8;
            cpa(ds + 10240, d_Ch + gb, 16);
        }
    };

    issue(0, 0); CP_COMMIT();
    issue(1, 1); CP_COMMIT();
    for (int ch = 0; ch < 4; ch++) {
        if (ch + 2 < 4) issue(ch + 2, (ch + 2) % NSTG);
        CP_COMMIT();
        CP_WAIT2();
        __syncthreads();
        mma_block(sm, ch % NSTG, wm, wn, acc);
        __syncthreads();
    }
    CP_WAIT0();
    __syncthreads();

    float* sC = (float*)sm;
    #pragma unroll
    for (int i = 0; i < 2; i++)
        #pragma unroll
        for (int j = 0; j < 4; j++)
            wmma::store_matrix_sync(&sC[(wm + i * 16) * 132 + wn + j * 16],
                                    acc[i][j], 132, wmma::mem_row_major);
    __syncthreads();
    int sel = n0 >> 7;   // 0:k(f32), 1:q(f16), 2:v(f16), 3:skip(f32)
    for (int t = tid; t < 4096; t += 256) {
        int row = t >> 5, c4 = (t & 31) << 2;
        int gr = m0 + row;
        if (gr >= NNODES) continue;
        const float* p = &sC[row * 132 + c4];
        int c = n0 + c4;
        float v0 = p[0] + d_bcat[c],     v1 = p[1] + d_bcat[c + 1];
        float v2 = p[2] + d_bcat[c + 2], v3 = p[3] + d_bcat[c + 3];
        if (sel == 0 || sel == 3) {
            float* dst = &d_kskip[(size_t)gr * 256 + ((sel == 0) ? c4 : 128 + c4)];
            *(float4*)dst = make_float4(v0, v1, v2, v3);
        } else {
            __align__(8) __half hv[4];
            hv[0] = __float2half(v0); hv[1] = __float2half(v1);
            hv[2] = __float2half(v2); hv[3] = __float2half(v3);
            __half* dst = &d_qvh[(size_t)gr * 256 + ((sel == 1) ? c4 : 128 + c4)];
            *(uint2*)dst = *(uint2*)hv;
        }
    }
}

// ---------------- gate: fp32 k/skip, fp16 q/v ----------------
__global__ void gate_kernel(float* __restrict__ out) {
    int dst = blockIdx.x * 8 + (threadIdx.x >> 5);
    if (dst >= NNODES) return;
    int lane = threadIdx.x & 31;
    const float4* ks4 = reinterpret_cast<const float4*>(d_kskip);   // 64 float4/row
    const uint2*  qv2 = reinterpret_cast<const uint2*>(d_qvh);      // 64 uint2/row (4 halves each)
    float4 kd  = ks4[(size_t)dst * 64 + lane];
    float4 acc = ks4[(size_t)dst * 64 + 32 + lane];
    int beg = d_off[dst * NREL];
    int end = d_off[dst * NREL + NREL];
    for (int e = beg; e < end; e++) {
        int s = d_ssrc[e];
        uint2 qr = __ldg(&qv2[(size_t)s * 64 + lane]);
        uint2 vr = __ldg(&qv2[(size_t)s * 64 + 32 + lane]);
        float2 q01 = __half22float2(*(const __half2*)&qr.x);
        float2 q23 = __half22float2(*(const __half2*)&qr.y);
        float2 v01 = __half22float2(*(const __half2*)&vr.x);
        float2 v23 = __half22float2(*(const __half2*)&vr.y);
        acc.x += v01.x * sigf(kd.x + q01.x);
        acc.y += v01.y * sigf(kd.y + q01.y);
        acc.z += v23.x * sigf(kd.z + q23.x);
        acc.w += v23.y * sigf(kd.w + q23.y);
    }
    reinterpret_cast<float4*>(out)[(size_t)dst * 32 + lane] = acc;
}

// ---------------- launcher ----------------
extern "C" void kernel_launch(void* const* d_in, const int* in_sizes, int n_in,
                              void* d_out, int out_size) {
    const float* x     = (const float*)d_in[0];
    const int*   ei    = (const int*)  d_in[1];
    const int*   etype = (const int*)  d_in[3];
    const float* basis = (const float*)d_in[4];
    const float* comp  = (const float*)d_in[5];
    const float* root  = (const float*)d_in[6];
    const float* bias1 = (const float*)d_in[7];
    const float* wk = (const float*)d_in[8];  const float* bk = (const float*)d_in[9];
    const float* wq = (const float*)d_in[10]; const float* bq = (const float*)d_in[11];
    const float* wv = (const float*)d_in[12]; const float* bv = (const float*)d_in[13];
    const float* ws = (const float*)d_in[14]; const float* bs = (const float*)d_in[15];
    float* out = (float*)d_out;

    cudaFuncSetAttribute(gemm1_wmma, cudaFuncAttributeMaxDynamicSharedMemorySize, GSMEM);
    cudaFuncSetAttribute(gemm2_wmma, cudaFuncAttributeMaxDynamicSharedMemorySize, GSMEM);

    build_BT<<<(128 * NK + 255) / 256, 256>>>(comp, basis, root);
    pack_CT<<<(512 * 128 + 255) / 256, 256>>>(wk, bk, wq, bq, wv, bv, ws, bs);

    zero_cnt<<<(RN + 255) / 256, 256>>>();
    count_edges<<<(NEDGES + 255) / 256, 256>>>(ei, etype);
    scan_blocksum<<<NSCAN, SCAN_B>>>();
    scan_partials<<<1, SCAN_B>>>();
    scan_final<<<NSCAN, SCAN_B>>>();
    scatter_edges<<<(NEDGES + 255) / 256, 256>>>(ei, etype);

    xsplit<<<(NNODES * 32 + 255) / 256, 256>>>(x);
    agg_split<<<RN / 8, 256>>>(x);

    gemm1_wmma<<<dim3(MT, KZ), 256, GSMEM>>>();
    finish_h<<<(NNODES * 32 + 511) / 512, 512>>>(bias1);
    gemm2_wmma<<<dim3(MT, 4), 256, GSMEM>>>();

    gate_kernel<<<(NNODES + 7) / 8, 256>>>(out);
}